// round 5
// baseline (speedup 1.0000x reference)
#include <cuda_runtime.h>
#include <cuda_bf16.h>
#include <cstdint>

#define NN 100000
#define EE 1600000
#define HD 128
#define NBLK 391   // ceil(NN/256)
#define NSTAT 512  // bn partial blocks

// ---------------- scratch (device globals; no allocations) ----------------
__device__ int   g_is32;
__device__ int   g_degi[NN];
__device__ float g_dis[NN];
__device__ int   g_rowptr[NN + 1];
__device__ int   g_cursor[NN];
__device__ int   g_bsums[512];
__device__ int   g_csr_src[EE];
__device__ float g_csr_w[EE];
__device__ float g_h[(size_t)NN * HD];
__device__ float g_z[(size_t)NN * HD];
__device__ float g_part1[NSTAT * HD];
__device__ float g_part2[NSTAT * HD];
__device__ float g_scale[HD];
__device__ float g_shift[HD];

// ---------------- edge-index dtype detection ----------------
// JAX default config downcasts int64 -> int32. Detect actual layout:
// int32 ids in [0,1e5) fused pairwise into int64 are >= 2^32 (unless the
// second word is 0), so any out-of-range value => int32 layout.
__global__ void detect_k(const void* ei) {
    const long long* p = (const long long*)ei;
    int is32 = 0;
#pragma unroll
    for (int i = 0; i < 16; i++) {
        long long v = p[i];  // in-bounds under either layout
        if (v < 0 || v >= NN) is32 = 1;
    }
    g_is32 = is32;
}

__device__ __forceinline__ int edge_at(const void* ei, size_t pos) {
    if (g_is32) return ((const int*)ei)[pos];
    return (int)((const long long*)ei)[pos];
}

// ---------------- CSR build ----------------
__global__ void deg_zero_k() {
    int i = blockIdx.x * blockDim.x + threadIdx.x;
    if (i < NN) g_degi[i] = 0;
}

__global__ void count_deg_k(const void* __restrict__ ei) {
    int e = blockIdx.x * blockDim.x + threadIdx.x;
    if (e < EE) atomicAdd(&g_degi[edge_at(ei, (size_t)EE + e)], 1);
}

__global__ void __launch_bounds__(256) block_red_k() {
    __shared__ int sm[256];
    int tid = threadIdx.x;
    int i = blockIdx.x * 256 + tid;
    sm[tid] = (i < NN) ? g_degi[i] : 0;
    __syncthreads();
    for (int off = 128; off > 0; off >>= 1) {
        if (tid < off) sm[tid] += sm[tid + off];
        __syncthreads();
    }
    if (tid == 0) g_bsums[blockIdx.x] = sm[0];
}

__global__ void __launch_bounds__(512) scan_sums_k() {
    __shared__ int sm[512];
    int tid = threadIdx.x;
    int v = (tid < NBLK) ? g_bsums[tid] : 0;
    sm[tid] = v;
    __syncthreads();
    for (int off = 1; off < 512; off <<= 1) {
        int add = (tid >= off) ? sm[tid - off] : 0;
        __syncthreads();
        sm[tid] += add;
        __syncthreads();
    }
    if (tid < NBLK) g_bsums[tid] = sm[tid] - v;  // exclusive
}

__global__ void __launch_bounds__(256) rowptr_k() {
    __shared__ int sm[256];
    int tid = threadIdx.x;
    int i = blockIdx.x * 256 + tid;
    int v = (i < NN) ? g_degi[i] : 0;
    sm[tid] = v;
    __syncthreads();
    for (int off = 1; off < 256; off <<= 1) {
        int add = (tid >= off) ? sm[tid - off] : 0;
        __syncthreads();
        sm[tid] += add;
        __syncthreads();
    }
    if (i < NN) {
        int base = g_bsums[blockIdx.x];
        g_rowptr[i] = base + sm[tid] - v;
        if (i == NN - 1) g_rowptr[NN] = base + sm[tid];
        g_cursor[i] = 0;
        g_dis[i] = rsqrtf((float)v + 1.0f);  // +1 self loop
    }
}

__global__ void csr_fill_k(const void* __restrict__ ei) {
    int e = blockIdx.x * blockDim.x + threadIdx.x;
    if (e >= EE) return;
    int r = edge_at(ei, e);
    int c = edge_at(ei, (size_t)EE + e);
    int pos = g_rowptr[c] + atomicAdd(&g_cursor[c], 1);
    g_csr_src[pos] = r;
    g_csr_w[pos] = g_dis[r] * g_dis[c];
}

// ---------------- GEMM: g_h = f(A) @ W ----------------
// A = Ain if non-null else g_z.  f = identity, or relu(a*scale+shift) if use_bn.
// K-split: W staged in 32KB static smem as two 64x128 halves.
__global__ void __launch_bounds__(256) gemm128_k(const float* __restrict__ Ain,
                                                 const float* __restrict__ W,
                                                 int use_bn) {
    __shared__ float Ws[64 * HD];  // 32 KB
    int tid = threadIdx.x;
    int warp = tid >> 5;
    int lane = tid & 31;
    int row0 = blockIdx.x * 64 + warp * 8;
    const float* A = Ain ? Ain : g_z;

    float4 sc = make_float4(1.f, 1.f, 1.f, 1.f);
    float4 sh = make_float4(0.f, 0.f, 0.f, 0.f);
    if (use_bn) {
        sc = ((const float4*)g_scale)[lane];
        sh = ((const float4*)g_shift)[lane];
    }

    float4 xf[8], acc[8];
#pragma unroll
    for (int rr = 0; rr < 8; rr++) {
        int r = row0 + rr;
        if (r < NN) {
            float4 v = ((const float4*)(A + (size_t)r * HD))[lane];
            if (use_bn) {
                v.x = fmaxf(fmaf(v.x, sc.x, sh.x), 0.f);
                v.y = fmaxf(fmaf(v.y, sc.y, sh.y), 0.f);
                v.z = fmaxf(fmaf(v.z, sc.z, sh.z), 0.f);
                v.w = fmaxf(fmaf(v.w, sc.w, sh.w), 0.f);
            }
            xf[rr] = v;
        } else {
            xf[rr] = make_float4(0.f, 0.f, 0.f, 0.f);
        }
        acc[rr] = make_float4(0.f, 0.f, 0.f, 0.f);
    }

    for (int half = 0; half < 2; half++) {
        __syncthreads();
        for (int i = tid; i < 64 * HD; i += 256) Ws[i] = W[half * 64 * HD + i];
        __syncthreads();
#pragma unroll 8
        for (int k = 0; k < 64; k++) {
            float4 wv = *(const float4*)(Ws + k * HD + 4 * lane);
            int srcLane = (half << 4) + (k >> 2);
#pragma unroll
            for (int rr = 0; rr < 8; rr++) {
                float xe;
                switch (k & 3) {
                    case 0: xe = xf[rr].x; break;
                    case 1: xe = xf[rr].y; break;
                    case 2: xe = xf[rr].z; break;
                    default: xe = xf[rr].w; break;
                }
                float xk = __shfl_sync(0xffffffffu, xe, srcLane);
                acc[rr].x = fmaf(xk, wv.x, acc[rr].x);
                acc[rr].y = fmaf(xk, wv.y, acc[rr].y);
                acc[rr].z = fmaf(xk, wv.z, acc[rr].z);
                acc[rr].w = fmaf(xk, wv.w, acc[rr].w);
            }
        }
    }

#pragma unroll
    for (int rr = 0; rr < 8; rr++) {
        int r = row0 + rr;
        if (r < NN) ((float4*)g_h)[(size_t)r * 32 + lane] = acc[rr];
    }
}

// ---------------- aggregation (gather, no atomics) ----------------
// one warp per node: dst[n] = h[n]*dis[n]^2 + b + sum_in_edges w * h[src]
__global__ void __launch_bounds__(256) aggregate_k(const float* __restrict__ b,
                                                   float* __restrict__ outp) {
    int warp = threadIdx.x >> 5;
    int lane = threadIdx.x & 31;
    int n = blockIdx.x * 8 + warp;
    if (n >= NN) return;

    const float4* h4 = (const float4*)g_h;
    float d = g_dis[n];
    float s = d * d;
    float4 bv = ((const float4*)b)[lane];
    float4 acc = h4[(size_t)n * 32 + lane];
    acc.x = fmaf(acc.x, s, bv.x);
    acc.y = fmaf(acc.y, s, bv.y);
    acc.z = fmaf(acc.z, s, bv.z);
    acc.w = fmaf(acc.w, s, bv.w);

    int p0 = g_rowptr[n];
    int p1 = g_rowptr[n + 1];
    for (int p = p0; p < p1; p++) {
        int src = g_csr_src[p];
        float wt = g_csr_w[p];
        float4 v = h4[(size_t)src * 32 + lane];
        acc.x = fmaf(wt, v.x, acc.x);
        acc.y = fmaf(wt, v.y, acc.y);
        acc.z = fmaf(wt, v.z, acc.z);
        acc.w = fmaf(wt, v.w, acc.w);
    }
    float* dst = outp ? outp : g_z;
    ((float4*)dst)[(size_t)n * 32 + lane] = acc;
}

// ---------------- batchnorm stats (no atomics) ----------------
__global__ void __launch_bounds__(128) bn_stats_k() {
    int j = threadIdx.x;
    float sum = 0.f, sq = 0.f;
    for (int r = blockIdx.x; r < NN; r += NSTAT) {
        float v = g_z[(size_t)r * HD + j];
        sum += v;
        sq = fmaf(v, v, sq);
    }
    g_part1[blockIdx.x * HD + j] = sum;
    g_part2[blockIdx.x * HD + j] = sq;
}

__global__ void __launch_bounds__(128) bn_final_k(const float* __restrict__ g,
                                                  const float* __restrict__ be) {
    int j = threadIdx.x;
    float s1 = 0.f, s2 = 0.f;
#pragma unroll 8
    for (int i = 0; i < NSTAT; i++) {
        s1 += g_part1[i * HD + j];
        s2 += g_part2[i * HD + j];
    }
    float inv_n = 1.0f / (float)NN;
    float mu = s1 * inv_n;
    float var = s2 * inv_n - mu * mu;
    float sc = g[j] * rsqrtf(var + 1e-5f);
    g_scale[j] = sc;
    g_shift[j] = be[j] - mu * sc;
}

// ---------------- host: kernel launches ONLY ----------------
extern "C" void kernel_launch(void* const* d_in, const int* in_sizes, int n_in,
                              void* d_out, int out_size) {
    const float* x = (const float*)d_in[0];
    const void* ei = d_in[1];  // int32 or int64, detected on device
    const float* W1 = (const float*)d_in[2];
    const float* b1 = (const float*)d_in[3];
    const float* W2 = (const float*)d_in[4];
    const float* b2 = (const float*)d_in[5];
    const float* W3 = (const float*)d_in[6];
    const float* b3 = (const float*)d_in[7];
    const float* g1 = (const float*)d_in[8];
    const float* be1 = (const float*)d_in[9];
    const float* g2 = (const float*)d_in[10];
    const float* be2 = (const float*)d_in[11];
    float* out = (float*)d_out;

    const int TB = 256;
    int nb_nodes = (NN + TB - 1) / TB;   // 391
    int nb_edges = (EE + TB - 1) / TB;   // 6250
    int nb_gemm = (NN + 63) / 64;        // 1563
    int nb_agg = (NN + 7) / 8;           // 12500

    // ---- CSR build + norm precompute ----
    detect_k<<<1, 1>>>(ei);
    deg_zero_k<<<nb_nodes, TB>>>();
    count_deg_k<<<nb_edges, TB>>>(ei);
    block_red_k<<<NBLK, 256>>>();
    scan_sums_k<<<1, 512>>>();
    rowptr_k<<<NBLK, 256>>>();
    csr_fill_k<<<nb_edges, TB>>>(ei);

    // ---- layer 1 ----
    gemm128_k<<<nb_gemm, TB>>>(x, W1, 0);
    aggregate_k<<<nb_agg, TB>>>(b1, nullptr);
    bn_stats_k<<<NSTAT, 128>>>();
    bn_final_k<<<1, 128>>>(g1, be1);

    // ---- layer 2 (BN1+ReLU fused into GEMM A-load) ----
    gemm128_k<<<nb_gemm, TB>>>(nullptr, W2, 1);
    aggregate_k<<<nb_agg, TB>>>(b2, nullptr);
    bn_stats_k<<<NSTAT, 128>>>();
    bn_final_k<<<1, 128>>>(g2, be2);

    // ---- layer 3 (BN2+ReLU fused into GEMM A-load) ----
    gemm128_k<<<nb_gemm, TB>>>(nullptr, W3, 1);
    aggregate_k<<<nb_agg, TB>>>(b3, out);
}

// round 7
// speedup vs baseline: 1.2253x; 1.2253x over previous
#include <cuda_runtime.h>
#include <cuda_bf16.h>
#include <cstdint>

#define NN 100000
#define EE 1600000
#define HD 128
#define NBLK 391   // ceil(NN/256)
#define NSTAT 512  // bn partial blocks

// ---------------- scratch (device globals; no allocations) ----------------
__device__ int   g_is32;
__device__ int   g_degi[NN];
__device__ float g_dis[NN];
__device__ int   g_rowptr[NN + 1];
__device__ int   g_cursor[NN];
__device__ int   g_bsums[512];
__device__ int   g_csr_src[EE];
__device__ float g_csr_w[EE];
__device__ float g_h[(size_t)NN * HD];
__device__ float g_z[(size_t)NN * HD];
__device__ float g_part1[NSTAT * HD];
__device__ float g_part2[NSTAT * HD];
__device__ float g_scale[HD];
__device__ float g_shift[HD];

// ---------------- edge-index dtype detection ----------------
__global__ void detect_k(const void* ei) {
    const long long* p = (const long long*)ei;
    int is32 = 0;
#pragma unroll
    for (int i = 0; i < 16; i++) {
        long long v = p[i];
        if (v < 0 || v >= NN) is32 = 1;
    }
    g_is32 = is32;
}

__device__ __forceinline__ int edge_at(const void* ei, size_t pos) {
    if (g_is32) return ((const int*)ei)[pos];
    return (int)((const long long*)ei)[pos];
}

// ---------------- CSR build ----------------
__global__ void deg_zero_k() {
    int i = blockIdx.x * blockDim.x + threadIdx.x;
    if (i < NN) g_degi[i] = 0;
}

__global__ void count_deg_k(const void* __restrict__ ei) {
    int e = blockIdx.x * blockDim.x + threadIdx.x;
    if (e < EE) atomicAdd(&g_degi[edge_at(ei, (size_t)EE + e)], 1);
}

__global__ void __launch_bounds__(256) block_red_k() {
    __shared__ int sm[256];
    int tid = threadIdx.x;
    int i = blockIdx.x * 256 + tid;
    sm[tid] = (i < NN) ? g_degi[i] : 0;
    __syncthreads();
    for (int off = 128; off > 0; off >>= 1) {
        if (tid < off) sm[tid] += sm[tid + off];
        __syncthreads();
    }
    if (tid == 0) g_bsums[blockIdx.x] = sm[0];
}

__global__ void __launch_bounds__(512) scan_sums_k() {
    __shared__ int sm[512];
    int tid = threadIdx.x;
    int v = (tid < NBLK) ? g_bsums[tid] : 0;
    sm[tid] = v;
    __syncthreads();
    for (int off = 1; off < 512; off <<= 1) {
        int add = (tid >= off) ? sm[tid - off] : 0;
        __syncthreads();
        sm[tid] += add;
        __syncthreads();
    }
    if (tid < NBLK) g_bsums[tid] = sm[tid] - v;  // exclusive
}

__global__ void __launch_bounds__(256) rowptr_k() {
    __shared__ int sm[256];
    int tid = threadIdx.x;
    int i = blockIdx.x * 256 + tid;
    int v = (i < NN) ? g_degi[i] : 0;
    sm[tid] = v;
    __syncthreads();
    for (int off = 1; off < 256; off <<= 1) {
        int add = (tid >= off) ? sm[tid - off] : 0;
        __syncthreads();
        sm[tid] += add;
        __syncthreads();
    }
    if (i < NN) {
        int base = g_bsums[blockIdx.x];
        g_rowptr[i] = base + sm[tid] - v;
        if (i == NN - 1) g_rowptr[NN] = base + sm[tid];
        g_cursor[i] = 0;
        g_dis[i] = rsqrtf((float)v + 1.0f);  // +1 self loop
    }
}

__global__ void csr_fill_k(const void* __restrict__ ei) {
    int e = blockIdx.x * blockDim.x + threadIdx.x;
    if (e >= EE) return;
    int r = edge_at(ei, e);
    int c = edge_at(ei, (size_t)EE + e);
    int pos = g_rowptr[c] + atomicAdd(&g_cursor[c], 1);
    g_csr_src[pos] = r;
    g_csr_w[pos] = g_dis[r] * g_dis[c];
}

// ---------------- tf32 tensor-core GEMM: g_h = f(A) @ W ----------------
__device__ __forceinline__ uint32_t f2tf32(float f) {
    uint32_t u;
    asm("cvt.rna.tf32.f32 %0, %1;" : "=r"(u) : "f"(f));
    return u;
}

// Block: 128 rows x 128 cols, K in 4 chunks of 32. 256 threads = 8 warps.
// Warp w computes rows [16w,16w+16) x all 128 cols via m16n8k8 tf32 mma.
// As: row-major [128][36] (pad->conflict-free), Wt: W transposed [n][k] [128][36].
__global__ void __launch_bounds__(256) gemm_tc_k(const float* __restrict__ Ain,
                                                 const float* __restrict__ W,
                                                 int use_bn) {
    __shared__ uint32_t As[128 * 36];  // 18 KB
    __shared__ uint32_t Wt[128 * 36];  // 18 KB
    const float* A = Ain ? Ain : g_z;
    int tid = threadIdx.x;
    int warp = tid >> 5, lane = tid & 31;
    int g = lane >> 2, tig = lane & 3;
    int row0 = blockIdx.x * 128;
    int wrow = warp * 16;

    float acc[16][4];
#pragma unroll
    for (int nt = 0; nt < 16; nt++)
#pragma unroll
        for (int i = 0; i < 4; i++) acc[nt][i] = 0.f;

    for (int kc = 0; kc < 4; kc++) {
        __syncthreads();
        // stage A chunk: rows [row0,row0+128) x cols [32kc,32kc+32), BN fused
        for (int i4 = tid; i4 < 128 * 8; i4 += 256) {
            int r = i4 >> 3, c4 = i4 & 7;
            int grow = row0 + r;
            float4 v = make_float4(0.f, 0.f, 0.f, 0.f);
            if (grow < NN)
                v = ((const float4*)(A + (size_t)grow * HD + kc * 32))[c4];
            if (use_bn) {
                float4 sc = ((const float4*)g_scale)[kc * 8 + c4];
                float4 sh = ((const float4*)g_shift)[kc * 8 + c4];
                v.x = fmaxf(fmaf(v.x, sc.x, sh.x), 0.f);
                v.y = fmaxf(fmaf(v.y, sc.y, sh.y), 0.f);
                v.z = fmaxf(fmaf(v.z, sc.z, sh.z), 0.f);
                v.w = fmaxf(fmaf(v.w, sc.w, sh.w), 0.f);
            }
            uint4 u = make_uint4(f2tf32(v.x), f2tf32(v.y), f2tf32(v.z), f2tf32(v.w));
            *(uint4*)(As + r * 36 + c4 * 4) = u;
        }
        // stage W chunk transposed: Wt[n][k] = W[32kc+k][n]
        for (int i = tid; i < 32 * 128; i += 256) {
            int k = i >> 7, n = i & 127;
            Wt[n * 36 + k] = f2tf32(W[(size_t)(kc * 32 + k) * HD + n]);
        }
        __syncthreads();

#pragma unroll
        for (int sub = 0; sub < 4; sub++) {
            int k8 = sub * 8;
            uint32_t a0 = As[(wrow + g) * 36 + k8 + tig];
            uint32_t a1 = As[(wrow + g + 8) * 36 + k8 + tig];
            uint32_t a2 = As[(wrow + g) * 36 + k8 + tig + 4];
            uint32_t a3 = As[(wrow + g + 8) * 36 + k8 + tig + 4];
#pragma unroll
            for (int nt = 0; nt < 16; nt++) {
                uint32_t b0 = Wt[(nt * 8 + g) * 36 + k8 + tig];
                uint32_t b1 = Wt[(nt * 8 + g) * 36 + k8 + tig + 4];
                asm volatile(
                    "mma.sync.aligned.m16n8k8.row.col.f32.tf32.tf32.f32 "
                    "{%0,%1,%2,%3}, {%4,%5,%6,%7}, {%8,%9}, {%0,%1,%2,%3};"
                    : "+f"(acc[nt][0]), "+f"(acc[nt][1]),
                      "+f"(acc[nt][2]), "+f"(acc[nt][3])
                    : "r"(a0), "r"(a1), "r"(a2), "r"(a3), "r"(b0), "r"(b1));
            }
        }
    }

    // epilogue: c0/c1 -> (row g, cols 2tig,2tig+1), c2/c3 -> row g+8
    int r0 = row0 + wrow + g;
    int r1 = r0 + 8;
#pragma unroll
    for (int nt = 0; nt < 16; nt++) {
        int col = nt * 8 + 2 * tig;
        if (r0 < NN)
            *(float2*)(g_h + (size_t)r0 * HD + col) = make_float2(acc[nt][0], acc[nt][1]);
        if (r1 < NN)
            *(float2*)(g_h + (size_t)r1 * HD + col) = make_float2(acc[nt][2], acc[nt][3]);
    }
}

// ---------------- aggregation (gather, no atomics) ----------------
__global__ void __launch_bounds__(256) aggregate_k(const float* __restrict__ b,
                                                   float* __restrict__ outp) {
    int warp = threadIdx.x >> 5;
    int lane = threadIdx.x & 31;
    int n = blockIdx.x * 8 + warp;
    if (n >= NN) return;

    const float4* h4 = (const float4*)g_h;
    float d = g_dis[n];
    float s = d * d;
    float4 bv = ((const float4*)b)[lane];
    float4 acc = h4[(size_t)n * 32 + lane];
    acc.x = fmaf(acc.x, s, bv.x);
    acc.y = fmaf(acc.y, s, bv.y);
    acc.z = fmaf(acc.z, s, bv.z);
    acc.w = fmaf(acc.w, s, bv.w);

    int p0 = g_rowptr[n];
    int p1 = g_rowptr[n + 1];
    for (int p = p0; p < p1; p++) {
        int src = g_csr_src[p];
        float wt = g_csr_w[p];
        float4 v = h4[(size_t)src * 32 + lane];
        acc.x = fmaf(wt, v.x, acc.x);
        acc.y = fmaf(wt, v.y, acc.y);
        acc.z = fmaf(wt, v.z, acc.z);
        acc.w = fmaf(wt, v.w, acc.w);
    }
    float* dst = outp ? outp : g_z;
    ((float4*)dst)[(size_t)n * 32 + lane] = acc;
}

// ---------------- batchnorm stats (no atomics) ----------------
__global__ void __launch_bounds__(128) bn_stats_k() {
    int j = threadIdx.x;
    float sum = 0.f, sq = 0.f;
    for (int r = blockIdx.x; r < NN; r += NSTAT) {
        float v = g_z[(size_t)r * HD + j];
        sum += v;
        sq = fmaf(v, v, sq);
    }
    g_part1[blockIdx.x * HD + j] = sum;
    g_part2[blockIdx.x * HD + j] = sq;
}

__global__ void __launch_bounds__(128) bn_final_k(const float* __restrict__ g,
                                                  const float* __restrict__ be) {
    int j = threadIdx.x;
    float s1 = 0.f, s2 = 0.f;
#pragma unroll 8
    for (int i = 0; i < NSTAT; i++) {
        s1 += g_part1[i * HD + j];
        s2 += g_part2[i * HD + j];
    }
    float inv_n = 1.0f / (float)NN;
    float mu = s1 * inv_n;
    float var = s2 * inv_n - mu * mu;
    float sc = g[j] * rsqrtf(var + 1e-5f);
    g_scale[j] = sc;
    g_shift[j] = be[j] - mu * sc;
}

// ---------------- host: kernel launches ONLY ----------------
extern "C" void kernel_launch(void* const* d_in, const int* in_sizes, int n_in,
                              void* d_out, int out_size) {
    const float* x = (const float*)d_in[0];
    const void* ei = d_in[1];
    const float* W1 = (const float*)d_in[2];
    const float* b1 = (const float*)d_in[3];
    const float* W2 = (const float*)d_in[4];
    const float* b2 = (const float*)d_in[5];
    const float* W3 = (const float*)d_in[6];
    const float* b3 = (const float*)d_in[7];
    const float* g1 = (const float*)d_in[8];
    const float* be1 = (const float*)d_in[9];
    const float* g2 = (const float*)d_in[10];
    const float* be2 = (const float*)d_in[11];
    float* out = (float*)d_out;

    const int TB = 256;
    int nb_nodes = (NN + TB - 1) / TB;   // 391
    int nb_edges = (EE + TB - 1) / TB;   // 6250
    int nb_gemm = (NN + 127) / 128;      // 782
    int nb_agg = (NN + 7) / 8;           // 12500

    // ---- CSR build + norm precompute ----
    detect_k<<<1, 1>>>(ei);
    deg_zero_k<<<nb_nodes, TB>>>();
    count_deg_k<<<nb_edges, TB>>>(ei);
    block_red_k<<<NBLK, 256>>>();
    scan_sums_k<<<1, 512>>>();
    rowptr_k<<<NBLK, 256>>>();
    csr_fill_k<<<nb_edges, TB>>>(ei);

    // ---- layer 1 ----
    gemm_tc_k<<<nb_gemm, TB>>>(x, W1, 0);
    aggregate_k<<<nb_agg, TB>>>(b1, nullptr);
    bn_stats_k<<<NSTAT, 128>>>();
    bn_final_k<<<1, 128>>>(g1, be1);

    // ---- layer 2 (BN1+ReLU fused into GEMM A-stage) ----
    gemm_tc_k<<<nb_gemm, TB>>>(nullptr, W2, 1);
    aggregate_k<<<nb_agg, TB>>>(b2, nullptr);
    bn_stats_k<<<NSTAT, 128>>>();
    bn_final_k<<<1, 128>>>(g2, be2);

    // ---- layer 3 (BN2+ReLU fused into GEMM A-stage) ----
    gemm_tc_k<<<nb_gemm, TB>>>(nullptr, W3, 1);
    aggregate_k<<<nb_agg, TB>>>(b3, out);
}